// round 1
// baseline (speedup 1.0000x reference)
#include <cuda_runtime.h>
#include <math.h>

#define TSTEPS 128
#define NENV   64
#define HID    1024
#define HID3   (3 * HID)

// ---------------- scratch (static device allocations only) ----------------
__device__ float g_gi[TSTEPS * NENV * HID3];   // 8192 x 3072  (96 MB)
__device__ float g_ys[TSTEPS * NENV * HID];    // 8192 x 1024  (32 MB)
__device__ float g_h[2][NENV * HID];           // double-buffered hidden state

// ---------------- helpers ----------------
__device__ __forceinline__ float sigmoidf_(float x) {
    return 1.0f / (1.0f + expf(-x));
}

// ---------------- init / copy kernels ----------------
__global__ void init_h_kernel(const float* __restrict__ hxs) {
    int i = blockIdx.x * blockDim.x + threadIdx.x;
    if (i < NENV * HID) g_h[0][i] = hxs[i];
}

__global__ void copy_hlast_kernel(float* __restrict__ dst) {
    int i = blockIdx.x * blockDim.x + threadIdx.x;
    if (i < NENV * HID) dst[i] = g_h[0][i];  // after 128 steps, parity lands in buf 0
}

// ---------------- generic NT GEMM:  C[M,N] = A[M,K] * B[N,K]^T + bias, opt ReLU
// 128x128 tile, BK=8, 256 threads, 8x8 per-thread register tile.
// All dims are exact multiples (M=8192, N in {3072,1024}, K=1024) -> no guards.
template <bool RELU>
__global__ __launch_bounds__(256) void gemm_nt_bias(
    const float* __restrict__ A, const float* __restrict__ B,
    const float* __restrict__ bias, float* __restrict__ C,
    int M, int N, int K)
{
    __shared__ float As[8][128];
    __shared__ float Bs[8][128];

    const int tid = threadIdx.x;
    const int m0 = blockIdx.y * 128;
    const int n0 = blockIdx.x * 128;

    const int lr = tid >> 1;          // 0..127 : row within tile
    const int lc = (tid & 1) << 2;    // 0 or 4 : k offset (float4)

    const int tx = tid & 15;          // 0..15 : n sub-tile
    const int ty = tid >> 4;          // 0..15 : m sub-tile

    float acc[8][8];
#pragma unroll
    for (int i = 0; i < 8; i++)
#pragma unroll
        for (int j = 0; j < 8; j++) acc[i][j] = 0.0f;

    const float* Aptr = A + (size_t)(m0 + lr) * K + lc;
    const float* Bptr = B + (size_t)(n0 + lr) * K + lc;

    for (int k0 = 0; k0 < K; k0 += 8) {
        float4 av = *(const float4*)(Aptr + k0);
        float4 bv = *(const float4*)(Bptr + k0);
        As[lc + 0][lr] = av.x; As[lc + 1][lr] = av.y;
        As[lc + 2][lr] = av.z; As[lc + 3][lr] = av.w;
        Bs[lc + 0][lr] = bv.x; Bs[lc + 1][lr] = bv.y;
        Bs[lc + 2][lr] = bv.z; Bs[lc + 3][lr] = bv.w;
        __syncthreads();

#pragma unroll
        for (int k = 0; k < 8; k++) {
            float4 a0 = *(const float4*)&As[k][ty * 8];
            float4 a1 = *(const float4*)&As[k][ty * 8 + 4];
            float4 b0 = *(const float4*)&Bs[k][tx * 8];
            float4 b1 = *(const float4*)&Bs[k][tx * 8 + 4];
            float ra[8] = {a0.x, a0.y, a0.z, a0.w, a1.x, a1.y, a1.z, a1.w};
            float rb[8] = {b0.x, b0.y, b0.z, b0.w, b1.x, b1.y, b1.z, b1.w};
#pragma unroll
            for (int i = 0; i < 8; i++)
#pragma unroll
                for (int j = 0; j < 8; j++)
                    acc[i][j] += ra[i] * rb[j];
        }
        __syncthreads();
    }

#pragma unroll
    for (int i = 0; i < 8; i++) {
        int m = m0 + ty * 8 + i;
#pragma unroll
        for (int j = 0; j < 8; j++) {
            int n = n0 + tx * 8 + j;
            float v = acc[i][j] + bias[n];
            if (RELU) v = fmaxf(v, 0.0f);
            C[(size_t)m * N + n] = v;
        }
    }
}

// ---------------- GRU step kernel ----------------
// One launch per timestep t.
// gh = (h * mask) @ w_hh^T; gates; h_new -> g_h[par^1] and g_ys[t].
// Block: 16 j-values x 32 envs (env half by blockIdx.y). 128 threads.
// Per thread: 1 j, 4 envs, 3 gates = 12 accumulators.
#define BJ 16
__global__ __launch_bounds__(128) void gru_step_kernel(
    const float* __restrict__ done,
    const float* __restrict__ w_hh,
    const float* __restrict__ b_hh,
    int t, int par)
{
    __shared__ float h_sm[32][33];          // padded to avoid bank conflicts
    __shared__ float w_sm[3][BJ][33];
    __shared__ float msk_sm[32];

    const float* __restrict__ h_in = g_h[par];
    float* __restrict__ h_out = g_h[par ^ 1];

    const int tid = threadIdx.x;
    const int j0 = blockIdx.x * BJ;
    const int eb = blockIdx.y * 32;         // env base for this block

    const int jj = tid >> 3;                // 0..15
    const int el = (tid & 7) * 4;           // local env base: 0,4,...,28

    if (tid < 32) msk_sm[tid] = 1.0f - done[t * NENV + eb + tid];
    __syncthreads();

    float ar[4] = {0, 0, 0, 0}, az[4] = {0, 0, 0, 0}, an[4] = {0, 0, 0, 0};

    for (int kk = 0; kk < HID; kk += 32) {
        // load masked h chunk: 32 envs x 32 k = 256 float4, 2 per thread
#pragma unroll
        for (int q = 0; q < 2; q++) {
            int l = tid * 2 + q;            // 0..255
            int e = l >> 3;
            int c = (l & 7) << 2;
            float4 v = *(const float4*)&h_in[(size_t)(eb + e) * HID + kk + c];
            float m = msk_sm[e];
            h_sm[e][c + 0] = v.x * m;
            h_sm[e][c + 1] = v.y * m;
            h_sm[e][c + 2] = v.z * m;
            h_sm[e][c + 3] = v.w * m;
        }
        // load w chunk: 3 gates x 16 j x 32 k = 384 float4, 3 per thread
#pragma unroll
        for (int q = 0; q < 3; q++) {
            int l = tid + q * 128;          // 0..383
            int g = l >> 7;
            int rem = l & 127;
            int j = rem >> 3;
            int c = (rem & 7) << 2;
            float4 v = *(const float4*)&w_hh[(size_t)(g * HID + j0 + j) * HID + kk + c];
            w_sm[g][j][c + 0] = v.x;
            w_sm[g][j][c + 1] = v.y;
            w_sm[g][j][c + 2] = v.z;
            w_sm[g][j][c + 3] = v.w;
        }
        __syncthreads();

#pragma unroll
        for (int k = 0; k < 32; k++) {
            float wr = w_sm[0][jj][k];
            float wz = w_sm[1][jj][k];
            float wn = w_sm[2][jj][k];
#pragma unroll
            for (int e = 0; e < 4; e++) {
                float hv = h_sm[el + e][k];
                ar[e] = fmaf(wr, hv, ar[e]);
                az[e] = fmaf(wz, hv, az[e]);
                an[e] = fmaf(wn, hv, an[e]);
            }
        }
        __syncthreads();
    }

    const int j = j0 + jj;
    const float br = b_hh[j];
    const float bz = b_hh[HID + j];
    const float bn = b_hh[2 * HID + j];

#pragma unroll
    for (int e = 0; e < 4; e++) {
        const int le = el + e;
        const int env = eb + le;
        const float m = msk_sm[le];
        const float hprev = h_in[(size_t)env * HID + j] * m;
        const float* gi_row = &g_gi[(size_t)(t * NENV + env) * HID3];
        const float ir = gi_row[j];
        const float iz = gi_row[HID + j];
        const float inn = gi_row[2 * HID + j];
        const float r = sigmoidf_(ir + ar[e] + br);
        const float z = sigmoidf_(iz + az[e] + bz);
        const float n = tanhf(inn + r * (an[e] + bn));
        const float hn = (1.0f - z) * n + z * hprev;
        h_out[(size_t)env * HID + j] = hn;
        g_ys[(size_t)(t * NENV + env) * HID + j] = hn;
    }
}

// ---------------- launch ----------------
extern "C" void kernel_launch(void* const* d_in, const int* in_sizes, int n_in,
                              void* d_out, int out_size)
{
    const float* x     = (const float*)d_in[0];
    const float* hxs   = (const float*)d_in[1];
    const float* done  = (const float*)d_in[2];
    const float* w_ih  = (const float*)d_in[3];
    const float* w_hh  = (const float*)d_in[4];
    const float* b_ih  = (const float*)d_in[5];
    const float* b_hh  = (const float*)d_in[6];
    const float* w_out = (const float*)d_in[7];
    const float* b_out = (const float*)d_in[8];
    float* out = (float*)d_out;

    float *gi_p = nullptr, *ys_p = nullptr;
    cudaGetSymbolAddress((void**)&gi_p, g_gi);
    cudaGetSymbolAddress((void**)&ys_p, g_ys);

    const int M = TSTEPS * NENV;   // 8192

    // h0 = hxs
    init_h_kernel<<<(NENV * HID + 255) / 256, 256>>>(hxs);

    // gi = x @ w_ih^T + b_ih   (8192 x 3072, K=1024)
    gemm_nt_bias<false><<<dim3(HID3 / 128, M / 128), 256>>>(
        x, w_ih, b_ih, gi_p, M, HID3, HID);

    // sequential scan
    for (int t = 0; t < TSTEPS; t++) {
        gru_step_kernel<<<dim3(HID / BJ, 2), 128>>>(done, w_hh, b_hh, t, t & 1);
    }

    // out = relu(ys @ w_out^T + b_out)  (8192 x 1024, K=1024)
    gemm_nt_bias<true><<<dim3(HID / 128, M / 128), 256>>>(
        ys_p, w_out, b_out, out, M, HID, HID);

    // h_last
    copy_hlast_kernel<<<(NENV * HID + 255) / 256, 256>>>(out + (size_t)M * HID);
}

// round 2
// speedup vs baseline: 1.4896x; 1.4896x over previous
#include <cuda_runtime.h>
#include <math.h>
#include <stdint.h>

#define TSTEPS 128
#define NENV   64
#define HID    1024
#define HID3   (3 * HID)

#define G      128      // persistent scan CTAs (j-slices)
#define JPC    8        // hidden units (j) per CTA
#define CK     128      // h k-chunk staged in smem

// ---------------- scratch (static device allocations only) ----------------
__device__ float g_gi[TSTEPS * NENV * HID3];   // 96 MB
__device__ float g_ys[TSTEPS * NENV * HID];    // 32 MB
__device__ float g_h[2][NENV * HID];
__device__ unsigned g_count;

// ---------------- helpers ----------------
__device__ __forceinline__ float sigmoidf_(float x) {
    return 1.0f / (1.0f + expf(-x));
}
__device__ __forceinline__ void fma2(unsigned long long& c,
                                     unsigned long long a,
                                     unsigned long long b) {
    asm("fma.rn.f32x2 %0, %1, %2, %0;" : "+l"(c) : "l"(a), "l"(b));
}
__device__ __forceinline__ float lohi(unsigned long long v) {
    float lo = __uint_as_float((unsigned)(v & 0xffffffffull));
    float hi = __uint_as_float((unsigned)(v >> 32));
    return lo + hi;
}

// ---------------- init / copy ----------------
__global__ void init_kernel(const float* __restrict__ hxs) {
    int i = blockIdx.x * blockDim.x + threadIdx.x;
    if (i == 0) g_count = 0;
    if (i < NENV * HID) g_h[0][i] = hxs[i];
}
__global__ void copy_hlast_kernel(float* __restrict__ dst) {
    int i = blockIdx.x * blockDim.x + threadIdx.x;
    if (i < NENV * HID) dst[i] = g_h[0][i];   // t=127 writes parity 0
}

// ---------------- k-paired f32x2 NT GEMM ----------------
// C[M,N] = A[M,K] * B[N,K]^T + bias (opt ReLU).
// Block tile 128(m) x 64(n), BK=8, 256 threads, per-thread 8m x 4n f32x2 accs
// paired over k (even/odd partial sums) -> zero packing instructions.
template <bool RELU>
__global__ __launch_bounds__(256) void gemm2(
    const float* __restrict__ A, const float* __restrict__ B,
    const float* __restrict__ bias, float* __restrict__ C,
    int M, int N, int K)
{
    __shared__ float As[4][128][2];   // [k-pair][m][2]
    __shared__ float Bs[4][64][2];    // [k-pair][n][2]

    const int tid = threadIdx.x;
    const int m0 = blockIdx.y * 128;
    const int n0 = blockIdx.x * 64;

    const int tx = tid & 15;          // n sub-tile (4 n each)
    const int ty = tid >> 4;          // m sub-tile (8 m each)

    const int alr = tid >> 1;         // A load row 0..127
    const int alc = (tid & 1) << 2;   // k offset 0 or 4
    const int blr = tid >> 1;         // B load row (tid<128 only)

    unsigned long long acc[8][4];
#pragma unroll
    for (int i = 0; i < 8; i++)
#pragma unroll
        for (int j = 0; j < 4; j++) acc[i][j] = 0ull;

    const float* Ap = A + (size_t)(m0 + alr) * K + alc;
    const float* Bp = B + (size_t)(n0 + (blr & 63)) * K + alc;

    for (int k0 = 0; k0 < K; k0 += 8) {
        float4 av = *(const float4*)(Ap + k0);
        *(float2*)&As[(alc >> 1) + 0][alr][0] = make_float2(av.x, av.y);
        *(float2*)&As[(alc >> 1) + 1][alr][0] = make_float2(av.z, av.w);
        if (tid < 128) {
            float4 bv = *(const float4*)(Bp + k0);
            *(float2*)&Bs[(alc >> 1) + 0][blr][0] = make_float2(bv.x, bv.y);
            *(float2*)&Bs[(alc >> 1) + 1][blr][0] = make_float2(bv.z, bv.w);
        }
        __syncthreads();

#pragma unroll
        for (int kp = 0; kp < 4; kp++) {
            const ulonglong2* ap = (const ulonglong2*)&As[kp][ty * 8][0];
            const ulonglong2* bp = (const ulonglong2*)&Bs[kp][tx * 4][0];
            ulonglong2 a01 = ap[0], a23 = ap[1], a45 = ap[2], a67 = ap[3];
            ulonglong2 b01 = bp[0], b23 = bp[1];
            unsigned long long a[8] = {a01.x, a01.y, a23.x, a23.y,
                                       a45.x, a45.y, a67.x, a67.y};
            unsigned long long b[4] = {b01.x, b01.y, b23.x, b23.y};
#pragma unroll
            for (int i = 0; i < 8; i++)
#pragma unroll
                for (int j = 0; j < 4; j++)
                    fma2(acc[i][j], a[i], b[j]);
        }
        __syncthreads();
    }

    const float4 b4 = *(const float4*)&bias[n0 + tx * 4];
#pragma unroll
    for (int i = 0; i < 8; i++) {
        int m = m0 + ty * 8 + i;
        float4 v;
        v.x = lohi(acc[i][0]) + b4.x;
        v.y = lohi(acc[i][1]) + b4.y;
        v.z = lohi(acc[i][2]) + b4.z;
        v.w = lohi(acc[i][3]) + b4.w;
        if (RELU) {
            v.x = fmaxf(v.x, 0.f); v.y = fmaxf(v.y, 0.f);
            v.z = fmaxf(v.z, 0.f); v.w = fmaxf(v.w, 0.f);
        }
        *(float4*)&C[(size_t)m * N + n0 + tx * 4] = v;
    }
}

// ---------------- persistent GRU scan ----------------
// Grid of G=128 CTAs, each owns j in [blockIdx*8, +8). w_hh slice (24 rows,
// 96KB) cached in smem for ALL timesteps. Per step: stream h through smem in
// CK chunks (double-buffered), f32x2 k-paired dot products, gate math, grid
// barrier. h traffic via __ldcg/__stcg (L2-coherent across CTAs).
#define HROW (CK + 4)

__device__ __forceinline__ void load_h8(float4* pre, const float* __restrict__ h_in,
                                        int c, int tid) {
#pragma unroll
    for (int q = 0; q < 8; q++) {
        int idx = q * 256 + tid;          // 0..2047
        int e = idx >> 5;                 // env 0..63
        int k4 = idx & 31;                // f4 within chunk
        pre[q] = __ldcg((const float4*)&h_in[(size_t)e * HID + c * CK + k4 * 4]);
    }
}

__global__ __launch_bounds__(256) void scan_kernel(
    const float* __restrict__ done,
    const float* __restrict__ w_hh,
    const float* __restrict__ b_hh)
{
    extern __shared__ float sm[];
    float* w_sm = sm;                          // [3*JPC][HID] = 24576 floats
    float* h_sm = sm + 3 * JPC * HID;          // [2][64][HROW] = 16896 floats
    float* msk  = h_sm + 2 * 64 * HROW;        // [64]

    const int tid  = threadIdx.x;
    const int jloc = tid >> 5;                 // 0..7
    const int lane = tid & 31;                 // env lo index
    const int j0   = blockIdx.x * JPC;
    const int j    = j0 + jloc;

    // cache w_hh slice: rows r = g*8+jl -> global row g*HID + j0 + jl
#pragma unroll 4
    for (int r = 0; r < 3 * JPC; r++) {
        const float* src = &w_hh[(size_t)((r >> 3) * HID + j0 + (r & 7)) * HID];
        *(float4*)&w_sm[r * HID + tid * 4] = *(const float4*)&src[tid * 4];
    }
    const float br = b_hh[j];
    const float bz = b_hh[HID + j];
    const float bn = b_hh[2 * HID + j];

    unsigned target = 0;

    for (int t = 0; t < TSTEPS; t++) {
        const int par = t & 1;
        const float* __restrict__ h_in  = g_h[par];
        float* __restrict__       h_out = g_h[par ^ 1];

        if (tid < 64) msk[tid] = 1.0f - done[t * NENV + tid];
        __syncthreads();

        // prefetch epilogue operands (latency hidden under the K loop)
        const float* gib = g_gi + ((size_t)t * NENV) * HID3 + j;
        const float gi_r0 = __ldg(gib + (size_t)lane * HID3);
        const float gi_z0 = __ldg(gib + (size_t)lane * HID3 + HID);
        const float gi_n0 = __ldg(gib + (size_t)lane * HID3 + 2 * HID);
        const float gi_r1 = __ldg(gib + (size_t)(lane + 32) * HID3);
        const float gi_z1 = __ldg(gib + (size_t)(lane + 32) * HID3 + HID);
        const float gi_n1 = __ldg(gib + (size_t)(lane + 32) * HID3 + 2 * HID);
        const float hp0 = __ldcg(&h_in[(size_t)lane * HID + j]);
        const float hp1 = __ldcg(&h_in[(size_t)(lane + 32) * HID + j]);

        float4 pre[8];
        load_h8(pre, h_in, 0, tid);

        unsigned long long acc[3][2][2];
#pragma unroll
        for (int g = 0; g < 3; g++)
#pragma unroll
            for (int e = 0; e < 2; e++) { acc[g][e][0] = 0ull; acc[g][e][1] = 0ull; }

        for (int c = 0; c < HID / CK; c++) {
            float* hb = h_sm + (c & 1) * 64 * HROW;
            // store masked chunk
#pragma unroll
            for (int q = 0; q < 8; q++) {
                int idx = q * 256 + tid;
                int e = idx >> 5;
                int k4 = idx & 31;
                float m = msk[e];
                float4 v = pre[q];
                *(float4*)&hb[e * HROW + k4 * 4] =
                    make_float4(v.x * m, v.y * m, v.z * m, v.w * m);
            }
            __syncthreads();
            if (c + 1 < HID / CK) load_h8(pre, h_in, c + 1, tid);

            const float* hA = hb + lane * HROW;
            const float* hB = hb + (lane + 32) * HROW;
            const float* wR = w_sm + (0 * JPC + jloc) * HID + c * CK;
            const float* wZ = wR + JPC * HID;
            const float* wN = wZ + JPC * HID;

#pragma unroll 8
            for (int ki = 0; ki < CK; ki += 4) {
                ulonglong2 H0 = *(const ulonglong2*)(hA + ki);
                ulonglong2 H1 = *(const ulonglong2*)(hB + ki);
                ulonglong2 W;
                W = *(const ulonglong2*)(wR + ki);
                fma2(acc[0][0][0], H0.x, W.x); fma2(acc[0][0][1], H0.y, W.y);
                fma2(acc[0][1][0], H1.x, W.x); fma2(acc[0][1][1], H1.y, W.y);
                W = *(const ulonglong2*)(wZ + ki);
                fma2(acc[1][0][0], H0.x, W.x); fma2(acc[1][0][1], H0.y, W.y);
                fma2(acc[1][1][0], H1.x, W.x); fma2(acc[1][1][1], H1.y, W.y);
                W = *(const ulonglong2*)(wN + ki);
                fma2(acc[2][0][0], H0.x, W.x); fma2(acc[2][0][1], H0.y, W.y);
                fma2(acc[2][1][0], H1.x, W.x); fma2(acc[2][1][1], H1.y, W.y);
            }
            __syncthreads();
        }

        const float ar0 = lohi(acc[0][0][0]) + lohi(acc[0][0][1]);
        const float az0 = lohi(acc[1][0][0]) + lohi(acc[1][0][1]);
        const float an0 = lohi(acc[2][0][0]) + lohi(acc[2][0][1]);
        const float ar1 = lohi(acc[0][1][0]) + lohi(acc[0][1][1]);
        const float az1 = lohi(acc[1][1][0]) + lohi(acc[1][1][1]);
        const float an1 = lohi(acc[2][1][0]) + lohi(acc[2][1][1]);

        {
            const float m = msk[lane];
            const float hprev = hp0 * m;
            const float r = sigmoidf_(gi_r0 + ar0 + br);
            const float z = sigmoidf_(gi_z0 + az0 + bz);
            const float n = tanhf(gi_n0 + r * (an0 + bn));
            const float hn = (1.0f - z) * n + z * hprev;
            __stcg(&h_out[(size_t)lane * HID + j], hn);
            __stcg(&g_ys[((size_t)t * NENV + lane) * HID + j], hn);
        }
        {
            const float m = msk[lane + 32];
            const float hprev = hp1 * m;
            const float r = sigmoidf_(gi_r1 + ar1 + br);
            const float z = sigmoidf_(gi_z1 + az1 + bz);
            const float n = tanhf(gi_n1 + r * (an1 + bn));
            const float hn = (1.0f - z) * n + z * hprev;
            __stcg(&h_out[(size_t)(lane + 32) * HID + j], hn);
            __stcg(&g_ys[((size_t)t * NENV + lane + 32) * HID + j], hn);
        }

        // ---- grid barrier ----
        __threadfence();
        __syncthreads();
        target += G;
        if (tid == 0) {
            atomicAdd(&g_count, 1u);
            while (*(volatile unsigned*)&g_count < target) __nanosleep(64);
            __threadfence();
        }
        __syncthreads();
    }
}

// ---------------- launch ----------------
extern "C" void kernel_launch(void* const* d_in, const int* in_sizes, int n_in,
                              void* d_out, int out_size)
{
    const float* x     = (const float*)d_in[0];
    const float* hxs   = (const float*)d_in[1];
    const float* done  = (const float*)d_in[2];
    const float* w_ih  = (const float*)d_in[3];
    const float* w_hh  = (const float*)d_in[4];
    const float* b_ih  = (const float*)d_in[5];
    const float* b_hh  = (const float*)d_in[6];
    const float* w_out = (const float*)d_in[7];
    const float* b_out = (const float*)d_in[8];
    float* out = (float*)d_out;

    float *gi_p = nullptr, *ys_p = nullptr;
    cudaGetSymbolAddress((void**)&gi_p, g_gi);
    cudaGetSymbolAddress((void**)&ys_p, g_ys);

    const int M = TSTEPS * NENV;   // 8192
    const int SMEM_SCAN = (3 * JPC * HID + 2 * 64 * HROW + 64) * (int)sizeof(float);

    static bool attr_set = false;
    if (!attr_set) {
        cudaFuncSetAttribute(scan_kernel,
                             cudaFuncAttributeMaxDynamicSharedMemorySize, SMEM_SCAN);
        attr_set = true;
    }

    // h0 = hxs, barrier counter = 0
    init_kernel<<<(NENV * HID + 255) / 256, 256>>>(hxs);

    // gi = x @ w_ih^T + b_ih   (8192 x 3072, K=1024)
    gemm2<false><<<dim3(HID3 / 64, M / 128), 256>>>(x, w_ih, b_ih, gi_p, M, HID3, HID);

    // full 128-step scan, one persistent launch
    scan_kernel<<<G, 256, SMEM_SCAN>>>(done, w_hh, b_hh);

    // out = relu(ys @ w_out^T + b_out)  (8192 x 1024, K=1024)
    gemm2<true><<<dim3(HID / 64, M / 128), 256>>>(ys_p, w_out, b_out, out, M, HID, HID);

    // h_last
    copy_hlast_kernel<<<(NENV * HID + 255) / 256, 256>>>(out + (size_t)M * HID);
}